// round 4
// baseline (speedup 1.0000x reference)
#include <cuda_runtime.h>
#include <math.h>

#define T_ 16
#define B_ 16
#define C_ 8
#define H_ 128
#define W_ 128
#define HW_ (H_*W_)
#define TB_ (T_*B_)
#define BAND 16
#define NBAND (H_/BAND)
#define EXT (BAND+2)
#define W4_ (W_/4)

// Scratch (device globals — no allocations allowed)
__device__ float g_chmax[TB_*C_];
__device__ float g_chsum[TB_*C_];
__device__ float g_difsum[TB_];
__device__ float g_motsum[TB_];
__device__ float g_beta[TB_*C_];
__device__ float g_thr[TB_];

__device__ __forceinline__ float warpReduceSum(float v){
  #pragma unroll
  for (int o=16;o>0;o>>=1) v += __shfl_down_sync(0xffffffffu, v, o);
  return v;
}
__device__ __forceinline__ float warpReduceMax(float v){
  #pragma unroll
  for (int o=16;o>0;o>>=1) v = fmaxf(v, __shfl_down_sync(0xffffffffu, v, o));
  return v;
}

// valid result in thread 0 only; blockDim.x == 256 (8 warps)
__device__ float blockReduceSum(float v, float* buf){
  int tid=threadIdx.x, lane=tid&31, warp=tid>>5;
  v = warpReduceSum(v);
  __syncthreads();
  if (lane==0) buf[warp]=v;
  __syncthreads();
  if (warp==0){
    v = (lane < 8) ? buf[lane] : 0.f;
    v = warpReduceSum(v);
  }
  return v;
}
__device__ float blockReduceMax(float v, float* buf){
  int tid=threadIdx.x, lane=tid&31, warp=tid>>5;
  v = warpReduceMax(v);
  __syncthreads();
  if (lane==0) buf[warp]=v;
  __syncthreads();
  if (warp==0){
    v = (lane < 8) ? buf[lane] : -3.402823466e38f;
    v = warpReduceMax(v);
  }
  return v;
}

// ---------------------------------------------------------------------------
// Phase 1: per-(t,b) statistics. One block per (t,b) image.
//   - per-channel max / sum (attention pooling)
//   - sum |x_t - x_{t-1}|  (temporal)
//   - sum over pixels of unfold-variance (motion), via smem cs/cs2 fields
// ---------------------------------------------------------------------------
__global__ void __launch_bounds__(256) phase1_kernel(const float* __restrict__ ev){
  const int tb = blockIdx.x;           // 0..255
  const int t  = tb / B_;
  const float* __restrict__ img  = ev + (size_t)tb * C_ * HW_;
  const float* __restrict__ prev = img - (size_t)B_ * C_ * HW_;   // valid iff t>0

  __shared__ float cs [EXT][W_];
  __shared__ float cs2[EXT][W_];
  __shared__ float rbuf[8];

  float chmax[C_], chsum[C_];
  #pragma unroll
  for (int c=0;c<C_;c++){ chmax[c] = -3.402823466e38f; chsum[c] = 0.f; }
  float difsum = 0.f, motsum = 0.f;
  const int tid = threadIdx.x;

  for (int band=0; band<NBAND; band++){
    const int r0 = band*BAND;
    // pass A: channel-sum / channel-sumsq fields for rows r0-1 .. r0+BAND
    for (int idx=tid; idx<EXT*W_; idx+=256){
      const int er = idx / W_;
      const int w  = idx % W_;
      const int r  = r0 - 1 + er;
      float s = 0.f, s2v = 0.f;
      if (r>=0 && r<H_){
        const bool inband = (er>=1 && er<=BAND);
        #pragma unroll
        for (int c=0;c<C_;c++){
          const float x = img[c*HW_ + r*W_ + w];
          s   += x;
          s2v += x*x;
          if (inband){
            chmax[c] = fmaxf(chmax[c], x);
            chsum[c] += x;
            if (t>0){
              const float xp = prev[c*HW_ + r*W_ + w];
              difsum += fabsf(x - xp);
            }
          }
        }
      }
      cs [er][w] = s;
      cs2[er][w] = s2v;
    }
    __syncthreads();
    // pass B: 3x3 neighborhood sums -> variance (n = C*9 = 72, ddof=1)
    for (int idx=tid; idx<BAND*W_; idx+=256){
      const int j  = idx / W_;
      const int w  = idx % W_;
      const int er = j + 1;
      float s1 = 0.f, s2 = 0.f;
      #pragma unroll
      for (int dy=-1; dy<=1; dy++){
        if (w>0)     { s1 += cs[er+dy][w-1]; s2 += cs2[er+dy][w-1]; }
                       s1 += cs[er+dy][w  ]; s2 += cs2[er+dy][w  ];
        if (w<W_-1)  { s1 += cs[er+dy][w+1]; s2 += cs2[er+dy][w+1]; }
      }
      const float var = (s2 - s1*s1*(1.0f/72.0f)) * (1.0f/71.0f);
      motsum += var;
    }
    __syncthreads();
  }

  #pragma unroll
  for (int c=0;c<C_;c++){
    float s = blockReduceSum(chsum[c], rbuf);
    if (tid==0) g_chsum[tb*C_+c] = s;
  }
  #pragma unroll
  for (int c=0;c<C_;c++){
    float m = blockReduceMax(chmax[c], rbuf);
    if (tid==0) g_chmax[tb*C_+c] = m;
  }
  {
    float d = blockReduceSum(difsum, rbuf);
    if (tid==0) g_difsum[tb] = d;
  }
  {
    float m = blockReduceSum(motsum, rbuf);
    if (tid==0) g_motsum[tb] = m;
  }
}

// ---------------------------------------------------------------------------
// Phase 2: tiny MLP (hidden=1) -> beta per (t,b,c); threshold per (t,b).
// One block of 256 threads, one thread per (t,b).
// ---------------------------------------------------------------------------
__device__ __forceinline__ float sigmoidf_(float x){ return 1.f/(1.f+expf(-x)); }

__global__ void phase2_kernel(const float* __restrict__ att_w1,
                              const float* __restrict__ att_w2,
                              const float* __restrict__ dw,
                              const float* __restrict__ tw,
                              const float* __restrict__ mw){
  const int tb = threadIdx.x;          // 0..255
  const int t  = tb / B_;

  float mx[C_], av[C_];
  float csum_all = 0.f;
  #pragma unroll
  for (int c=0;c<C_;c++){
    mx[c] = g_chmax[tb*C_+c];
    const float s = g_chsum[tb*C_+c];
    av[c] = s * (1.0f/(float)HW_);
    csum_all += s;
  }
  // h = relu([mx, av] @ w1.T), hidden = 1, w1 shape (1, 2C)
  float h = 0.f;
  #pragma unroll
  for (int c=0;c<C_;c++) h += mx[c]*att_w1[c];
  #pragma unroll
  for (int c=0;c<C_;c++) h += av[c]*att_w1[C_+c];
  h = fmaxf(h, 0.f);
  #pragma unroll
  for (int c=0;c<C_;c++)
    g_beta[tb*C_+c] = 0.5f + 0.45f*sigmoidf_(h*att_w2[c]);

  const float density  = csum_all * (1.0f/((float)C_*HW_));
  const float temporal = (t==0) ? 0.f : g_difsum[tb] * (1.0f/((float)C_*HW_));
  const float motion   = g_motsum[tb] * (1.0f/(float)HW_);
  const float adj = sigmoidf_(dw[0]*density + tw[0]*temporal + mw[0]*motion) * 2.0f;
  g_thr[tb] = 1.0f + adj;
}

// ---------------------------------------------------------------------------
// Phase 3: fused depthwise 3x3 conv + sequential LIF scan over T.
// grid = (band, c, b); block = 256 threads; v-state in registers across t.
// Band rows are 512B, 16B-aligned -> float4 smem fill.
// ---------------------------------------------------------------------------
__global__ void __launch_bounds__(256) phase3_kernel(const float* __restrict__ ev,
                                                     const float* __restrict__ conv_w,
                                                     float* __restrict__ out){
  const int band = blockIdx.x;   // 0..7
  const int c    = blockIdx.y;   // 0..7
  const int b    = blockIdx.z;   // 0..15
  const int r0   = band*BAND;
  const int tid  = threadIdx.x;

  __shared__ float sm[EXT][W_];

  float wk[9];
  #pragma unroll
  for (int i=0;i<9;i++) wk[i] = conv_w[c*9+i];

  float v[8];
  #pragma unroll
  for (int k=0;k<8;k++) v[k] = 0.f;

  for (int t=0; t<T_; t++){
    const size_t base = ((size_t)(t*B_+b)*C_ + c) * HW_;
    const float* __restrict__ img = ev + base;

    // band fill: EXT*W4_ = 18*32 = 576 float4 loads across 256 threads
    for (int idx=tid; idx<EXT*W4_; idx+=256){
      const int er = idx / W4_;
      const int q  = idx % W4_;
      const int r  = r0 - 1 + er;
      float4 val = make_float4(0.f,0.f,0.f,0.f);
      if (r>=0 && r<H_)
        val = __ldg((const float4*)(img + r*W_) + q);
      *((float4*)&sm[er][0] + q) = val;
    }
    __syncthreads();

    const float beta = g_beta[(t*B_+b)*C_+c];
    const float omb  = 1.f - beta;
    const float thr  = g_thr[t*B_+b];
    float* __restrict__ o = out + base + (size_t)r0*W_;

    #pragma unroll
    for (int k=0;k<8;k++){
      const int idx = tid + k*256;          // 0..2047 within band
      const int j   = idx / W_;
      const int w   = idx % W_;
      const int er  = j + 1;

      float wi = sm[er-1][w]*wk[1] + sm[er][w]*wk[4] + sm[er+1][w]*wk[7];
      if (w > 0)
        wi += sm[er-1][w-1]*wk[0] + sm[er][w-1]*wk[3] + sm[er+1][w-1]*wk[6];
      if (w < W_-1)
        wi += sm[er-1][w+1]*wk[2] + sm[er][w+1]*wk[5] + sm[er+1][w+1]*wk[8];

      const float x  = sm[er][w];
      float vv = beta*v[k] + omb*wi;                          // charge
      const float spike = atanf(2.f*(vv - thr))*0.5f + 0.5f;  // atan surrogate
      vv = (1.f - spike)*vv;                                  // reset
      v[k] = vv;
      o[idx] = x * spike;                                     // cur * spike
    }
    __syncthreads();
  }
}

// ---------------------------------------------------------------------------
extern "C" void kernel_launch(void* const* d_in, const int* in_sizes, int n_in,
                              void* d_out, int out_size){
  const float* ev     = (const float*)d_in[0];
  const float* conv_w = (const float*)d_in[1];
  const float* att_w1 = (const float*)d_in[2];
  const float* att_w2 = (const float*)d_in[3];
  const float* dw     = (const float*)d_in[4];
  const float* tw     = (const float*)d_in[5];
  const float* mw     = (const float*)d_in[6];
  float* out = (float*)d_out;

  phase1_kernel<<<TB_, 256>>>(ev);
  phase2_kernel<<<1, TB_>>>(att_w1, att_w2, dw, tw, mw);
  dim3 g3(NBAND, C_, B_);
  phase3_kernel<<<g3, 256>>>(ev, conv_w, out);
}

// round 5
// speedup vs baseline: 1.8407x; 1.8407x over previous
#include <cuda_runtime.h>
#include <math.h>

#define T_ 16
#define B_ 16
#define C_ 8
#define H_ 128
#define W_ 128
#define HW_ (H_*W_)
#define TB_ (T_*B_)
#define W4_ (W_/4)

// phase1 band decomposition
#define BAND 16
#define NBAND (H_/BAND)
#define EXT (BAND+2)
#define NPART (TB_*NBAND)          // 2048 partials

// phase3 band decomposition
#define BAND3 8
#define NBAND3 (H_/BAND3)
#define EXT3 (BAND3+2)

// Scratch (device globals — no allocations allowed)
__device__ float g_part_chmax[NPART*C_];
__device__ float g_part_chsum[NPART*C_];
__device__ float g_part_dif[NPART];
__device__ float g_part_mot[NPART];
__device__ float g_beta[TB_*C_];
__device__ float g_thr[TB_];

__device__ __forceinline__ float warpReduceSum(float v){
  #pragma unroll
  for (int o=16;o>0;o>>=1) v += __shfl_down_sync(0xffffffffu, v, o);
  return v;
}
__device__ __forceinline__ float warpReduceMax(float v){
  #pragma unroll
  for (int o=16;o>0;o>>=1) v = fmaxf(v, __shfl_down_sync(0xffffffffu, v, o));
  return v;
}
// valid in thread 0 only; blockDim.x == 256 (8 warps)
__device__ float blockReduceSum(float v, float* buf){
  int tid=threadIdx.x, lane=tid&31, warp=tid>>5;
  v = warpReduceSum(v);
  __syncthreads();
  if (lane==0) buf[warp]=v;
  __syncthreads();
  if (warp==0){
    v = (lane < 8) ? buf[lane] : 0.f;
    v = warpReduceSum(v);
  }
  return v;
}
__device__ float blockReduceMax(float v, float* buf){
  int tid=threadIdx.x, lane=tid&31, warp=tid>>5;
  v = warpReduceMax(v);
  __syncthreads();
  if (lane==0) buf[warp]=v;
  __syncthreads();
  if (warp==0){
    v = (lane < 8) ? buf[lane] : -3.402823466e38f;
    v = warpReduceMax(v);
  }
  return v;
}

// ---------------------------------------------------------------------------
// Phase 1: per-(t,b,band) PARTIAL statistics. grid = (256 tb, 8 bands).
// Vectorized float4 loads throughout. Deterministic (no float atomics).
// ---------------------------------------------------------------------------
__global__ void __launch_bounds__(256) phase1_kernel(const float* __restrict__ ev){
  const int tb   = blockIdx.x;          // 0..255
  const int band = blockIdx.y;          // 0..7
  const int t    = tb / B_;
  const int r0   = band*BAND;
  const float* __restrict__ img  = ev + (size_t)tb * C_ * HW_;
  const float* __restrict__ prev = img - (size_t)B_ * C_ * HW_;   // valid iff t>0

  __shared__ float cs [EXT][W_];
  __shared__ float cs2[EXT][W_];
  __shared__ float rbuf[8];

  float chmax[C_], chsum[C_];
  #pragma unroll
  for (int c=0;c<C_;c++){ chmax[c] = -3.402823466e38f; chsum[c] = 0.f; }
  float difsum = 0.f, motsum = 0.f;
  const int tid = threadIdx.x;

  // pass A: channel-sum / channel-sumsq fields for rows r0-1 .. r0+BAND
  // EXT*W4_ = 18*32 = 576 float4 items
  for (int idx=tid; idx<EXT*W4_; idx+=256){
    const int er = idx / W4_;
    const int q  = idx % W4_;
    const int r  = r0 - 1 + er;
    float4 s  = make_float4(0.f,0.f,0.f,0.f);
    float4 s2 = make_float4(0.f,0.f,0.f,0.f);
    if (r>=0 && r<H_){
      const bool inband = (er>=1 && er<=BAND);
      #pragma unroll
      for (int c=0;c<C_;c++){
        const float4 x = __ldg((const float4*)(img + c*HW_ + r*W_) + q);
        s.x += x.x; s.y += x.y; s.z += x.z; s.w += x.w;
        s2.x += x.x*x.x; s2.y += x.y*x.y; s2.z += x.z*x.z; s2.w += x.w*x.w;
        if (inband){
          chmax[c] = fmaxf(chmax[c], fmaxf(fmaxf(x.x,x.y), fmaxf(x.z,x.w)));
          chsum[c] += (x.x + x.y) + (x.z + x.w);
          if (t>0){
            const float4 xp = __ldg((const float4*)(prev + c*HW_ + r*W_) + q);
            difsum += fabsf(x.x-xp.x) + fabsf(x.y-xp.y)
                    + fabsf(x.z-xp.z) + fabsf(x.w-xp.w);
          }
        }
      }
    }
    *((float4*)&cs [er][0] + q) = s;
    *((float4*)&cs2[er][0] + q) = s2;
  }
  __syncthreads();

  // pass B: 3x3 neighborhood sums -> variance (n = C*9 = 72, ddof=1)
  for (int idx=tid; idx<BAND*W_; idx+=256){
    const int j  = idx / W_;
    const int w  = idx % W_;
    const int er = j + 1;
    float s1 = 0.f, s2 = 0.f;
    #pragma unroll
    for (int dy=-1; dy<=1; dy++){
      if (w>0)     { s1 += cs[er+dy][w-1]; s2 += cs2[er+dy][w-1]; }
                     s1 += cs[er+dy][w  ]; s2 += cs2[er+dy][w  ];
      if (w<W_-1)  { s1 += cs[er+dy][w+1]; s2 += cs2[er+dy][w+1]; }
    }
    motsum += (s2 - s1*s1*(1.0f/72.0f)) * (1.0f/71.0f);
  }
  __syncthreads();

  // block reductions + write partials
  const int p = tb*NBAND + band;
  #pragma unroll
  for (int c=0;c<C_;c++){
    float s = blockReduceSum(chsum[c], rbuf);
    if (tid==0) g_part_chsum[p*C_+c] = s;
  }
  #pragma unroll
  for (int c=0;c<C_;c++){
    float m = blockReduceMax(chmax[c], rbuf);
    if (tid==0) g_part_chmax[p*C_+c] = m;
  }
  {
    float d = blockReduceSum(difsum, rbuf);
    if (tid==0) g_part_dif[p] = d;
  }
  {
    float m = blockReduceSum(motsum, rbuf);
    if (tid==0) g_part_mot[p] = m;
  }
}

// ---------------------------------------------------------------------------
// Phase 2: fold band partials; tiny MLP (hidden=1) -> beta; threshold.
// One block of 256 threads, one thread per (t,b).
// ---------------------------------------------------------------------------
__device__ __forceinline__ float sigmoidf_(float x){ return 1.f/(1.f+expf(-x)); }

__global__ void phase2_kernel(const float* __restrict__ att_w1,
                              const float* __restrict__ att_w2,
                              const float* __restrict__ dw,
                              const float* __restrict__ tw,
                              const float* __restrict__ mw){
  const int tb = threadIdx.x;          // 0..255
  const int t  = tb / B_;

  float mx[C_], sm_[C_];
  #pragma unroll
  for (int c=0;c<C_;c++){ mx[c] = -3.402823466e38f; sm_[c] = 0.f; }
  float difsum = 0.f, motsum = 0.f;

  #pragma unroll
  for (int band=0; band<NBAND; band++){
    const int p = tb*NBAND + band;
    #pragma unroll
    for (int c=0;c<C_;c++){
      mx[c]  = fmaxf(mx[c], g_part_chmax[p*C_+c]);
      sm_[c] += g_part_chsum[p*C_+c];
    }
    difsum += g_part_dif[p];
    motsum += g_part_mot[p];
  }

  float csum_all = 0.f;
  float av[C_];
  #pragma unroll
  for (int c=0;c<C_;c++){
    av[c] = sm_[c] * (1.0f/(float)HW_);
    csum_all += sm_[c];
  }
  // h = relu([mx, av] @ w1.T), hidden = 1, w1 shape (1, 2C)
  float h = 0.f;
  #pragma unroll
  for (int c=0;c<C_;c++) h += mx[c]*att_w1[c];
  #pragma unroll
  for (int c=0;c<C_;c++) h += av[c]*att_w1[C_+c];
  h = fmaxf(h, 0.f);
  #pragma unroll
  for (int c=0;c<C_;c++)
    g_beta[tb*C_+c] = 0.5f + 0.45f*sigmoidf_(h*att_w2[c]);

  const float density  = csum_all * (1.0f/((float)C_*HW_));
  const float temporal = (t==0) ? 0.f : difsum * (1.0f/((float)C_*HW_));
  const float motion   = motsum * (1.0f/(float)HW_);
  const float adj = sigmoidf_(dw[0]*density + tw[0]*temporal + mw[0]*motion) * 2.0f;
  g_thr[tb] = 1.0f + adj;
}

// ---------------------------------------------------------------------------
// Phase 3: fused depthwise 3x3 conv + sequential LIF scan over T.
// grid = (16 bands, 8 c, 16 b) = 2048 blocks; 8-row bands; v in registers.
// Software-pipelined: prefetch t+1 band into registers while computing t.
// ---------------------------------------------------------------------------
#define NLD3 (EXT3*W4_)   // 10*32 = 320 float4 items per band

__global__ void __launch_bounds__(256) phase3_kernel(const float* __restrict__ ev,
                                                     const float* __restrict__ conv_w,
                                                     float* __restrict__ out){
  const int band = blockIdx.x;   // 0..15
  const int c    = blockIdx.y;   // 0..7
  const int b    = blockIdx.z;   // 0..15
  const int r0   = band*BAND3;
  const int tid  = threadIdx.x;

  __shared__ float sm[EXT3][W_];

  float wk[9];
  #pragma unroll
  for (int i=0;i<9;i++) wk[i] = conv_w[c*9+i];

  float v[4];
  #pragma unroll
  for (int k=0;k<4;k++) v[k] = 0.f;

  // prefetch slots: item i0 = tid (<320 always since tid<256), i1 = tid+256 (<320 iff tid<64)
  const int i0 = tid, i1 = tid + 256;
  const int er0 = i0 / W4_, q0 = i0 % W4_, r_0 = r0 - 1 + er0;
  const int er1 = i1 / W4_, q1 = i1 % W4_, r_1 = r0 - 1 + er1;
  const bool has1 = (i1 < NLD3);
  const bool v0 = (r_0 >= 0 && r_0 < H_);
  const bool v1 = has1 && (r_1 >= 0 && r_1 < H_);

  float4 pf0 = make_float4(0.f,0.f,0.f,0.f);
  float4 pf1 = make_float4(0.f,0.f,0.f,0.f);

  // preload t = 0
  {
    const float* __restrict__ img = ev + ((size_t)b*C_ + c) * HW_;   // t=0
    if (v0) pf0 = __ldg((const float4*)(img + r_0*W_) + q0);
    if (v1) pf1 = __ldg((const float4*)(img + r_1*W_) + q1);
  }

  for (int t=0; t<T_; t++){
    // deposit prefetched band into smem
    *((float4*)&sm[er0][0] + q0) = pf0;
    if (has1) *((float4*)&sm[er1][0] + q1) = pf1;
    __syncthreads();

    // issue prefetch for t+1 (overlaps with compute below)
    if (t+1 < T_){
      const float* __restrict__ img = ev + ((size_t)((t+1)*B_+b)*C_ + c) * HW_;
      pf0 = v0 ? __ldg((const float4*)(img + r_0*W_) + q0) : make_float4(0.f,0.f,0.f,0.f);
      if (has1) pf1 = v1 ? __ldg((const float4*)(img + r_1*W_) + q1) : make_float4(0.f,0.f,0.f,0.f);
    }

    const float beta = g_beta[(t*B_+b)*C_+c];
    const float omb  = 1.f - beta;
    const float thr  = g_thr[t*B_+b];
    const size_t base = ((size_t)(t*B_+b)*C_ + c) * HW_;
    float* __restrict__ o = out + base + (size_t)r0*W_;

    #pragma unroll
    for (int k=0;k<4;k++){
      const int idx = tid + k*256;          // 0..1023 within band
      const int j   = idx / W_;
      const int w   = idx % W_;
      const int er  = j + 1;

      float wi = sm[er-1][w]*wk[1] + sm[er][w]*wk[4] + sm[er+1][w]*wk[7];
      if (w > 0)
        wi += sm[er-1][w-1]*wk[0] + sm[er][w-1]*wk[3] + sm[er+1][w-1]*wk[6];
      if (w < W_-1)
        wi += sm[er-1][w+1]*wk[2] + sm[er][w+1]*wk[5] + sm[er+1][w+1]*wk[8];

      const float x  = sm[er][w];
      float vv = beta*v[k] + omb*wi;                          // charge
      const float spike = atanf(2.f*(vv - thr))*0.5f + 0.5f;  // atan surrogate
      vv = (1.f - spike)*vv;                                  // reset
      v[k] = vv;
      o[idx] = x * spike;                                     // cur * spike
    }
    __syncthreads();   // protect smem before next deposit
  }
}

// ---------------------------------------------------------------------------
extern "C" void kernel_launch(void* const* d_in, const int* in_sizes, int n_in,
                              void* d_out, int out_size){
  const float* ev     = (const float*)d_in[0];
  const float* conv_w = (const float*)d_in[1];
  const float* att_w1 = (const float*)d_in[2];
  const float* att_w2 = (const float*)d_in[3];
  const float* dw     = (const float*)d_in[4];
  const float* tw     = (const float*)d_in[5];
  const float* mw     = (const float*)d_in[6];
  float* out = (float*)d_out;

  dim3 g1(TB_, NBAND);
  phase1_kernel<<<g1, 256>>>(ev);
  phase2_kernel<<<1, TB_>>>(att_w1, att_w2, dw, tw, mw);
  dim3 g3(NBAND3, C_, B_);
  phase3_kernel<<<g3, 256>>>(ev, conv_w, out);
}

// round 6
// speedup vs baseline: 2.3514x; 1.2775x over previous
#include <cuda_runtime.h>
#include <math.h>

#define T_ 16
#define B_ 16
#define C_ 8
#define H_ 128
#define W_ 128
#define HW_ (H_*W_)
#define TB_ (T_*B_)
#define W4_ (W_/4)

// phase1 band decomposition
#define BAND 16
#define NBAND (H_/BAND)
#define EXT (BAND+2)
#define NPART (TB_*NBAND)          // 2048 partials

// Scratch (device globals — no allocations allowed)
__device__ float g_part_chmax[NPART*C_];
__device__ float g_part_chsum[NPART*C_];
__device__ float g_part_dif[NPART];
__device__ float g_part_mot[NPART];
__device__ float g_beta[TB_*C_];
__device__ float g_thr[TB_];

__device__ __forceinline__ float warpReduceSum(float v){
  #pragma unroll
  for (int o=16;o>0;o>>=1) v += __shfl_down_sync(0xffffffffu, v, o);
  return v;
}
__device__ __forceinline__ float warpReduceMax(float v){
  #pragma unroll
  for (int o=16;o>0;o>>=1) v = fmaxf(v, __shfl_down_sync(0xffffffffu, v, o));
  return v;
}

// ---------------------------------------------------------------------------
// Phase 1: per-(t,b,band) PARTIAL statistics. grid = (256 tb, 8 bands).
// Branch-free pass A partition (inband vs halo), vectorized pass B,
// warp-reduce + single-smem-fold tail (2 syncs total).
// ---------------------------------------------------------------------------
__global__ void __launch_bounds__(256) phase1_kernel(const float* __restrict__ ev){
  const int tb   = blockIdx.x;          // 0..255
  const int band = blockIdx.y;          // 0..7
  const int t    = tb / B_;
  const int r0   = band*BAND;
  const float* __restrict__ img  = ev + (size_t)tb * C_ * HW_;
  const float* __restrict__ prev = img - (size_t)B_ * C_ * HW_;   // valid iff t>0

  __shared__ float cs [EXT][W_];
  __shared__ float cs2[EXT][W_];
  __shared__ float wbuf[8][18];

  const int tid  = threadIdx.x;
  const int lane = tid & 31;
  const int wrp  = tid >> 5;

  float chmax[C_], chsum[C_];
  #pragma unroll
  for (int c=0;c<C_;c++){ chmax[c] = -3.402823466e38f; chsum[c] = 0.f; }
  float difsum = 0.f, motsum = 0.f;

  // ---- pass A: inband items (rows r0..r0+15), all stats, branch-free ----
  #pragma unroll
  for (int it=0; it<2; it++){
    const int idx = tid + it*256;       // 0..511
    const int jr  = idx >> 5;           // 0..15
    const int q   = idx & 31;
    const int r   = r0 + jr;
    const int er  = jr + 1;
    float4 s  = make_float4(0.f,0.f,0.f,0.f);
    float4 s2 = make_float4(0.f,0.f,0.f,0.f);
    if (t > 0){
      #pragma unroll
      for (int c=0;c<C_;c++){
        const float4 x  = __ldg((const float4*)(img  + c*HW_ + r*W_) + q);
        const float4 xp = __ldg((const float4*)(prev + c*HW_ + r*W_) + q);
        s.x += x.x; s.y += x.y; s.z += x.z; s.w += x.w;
        s2.x = fmaf(x.x,x.x,s2.x); s2.y = fmaf(x.y,x.y,s2.y);
        s2.z = fmaf(x.z,x.z,s2.z); s2.w = fmaf(x.w,x.w,s2.w);
        chmax[c] = fmaxf(chmax[c], fmaxf(fmaxf(x.x,x.y), fmaxf(x.z,x.w)));
        chsum[c] += (x.x + x.y) + (x.z + x.w);
        difsum += fabsf(x.x-xp.x) + fabsf(x.y-xp.y)
                + fabsf(x.z-xp.z) + fabsf(x.w-xp.w);
      }
    } else {
      #pragma unroll
      for (int c=0;c<C_;c++){
        const float4 x = __ldg((const float4*)(img + c*HW_ + r*W_) + q);
        s.x += x.x; s.y += x.y; s.z += x.z; s.w += x.w;
        s2.x = fmaf(x.x,x.x,s2.x); s2.y = fmaf(x.y,x.y,s2.y);
        s2.z = fmaf(x.z,x.z,s2.z); s2.w = fmaf(x.w,x.w,s2.w);
        chmax[c] = fmaxf(chmax[c], fmaxf(fmaxf(x.x,x.y), fmaxf(x.z,x.w)));
        chsum[c] += (x.x + x.y) + (x.z + x.w);
      }
    }
    *((float4*)&cs [er][0] + q) = s;
    *((float4*)&cs2[er][0] + q) = s2;
  }
  // ---- pass A: halo rows (er=0 and er=17), cs/cs2 only ----
  if (tid < 64){
    const int h  = tid >> 5;            // 0 or 1
    const int q  = tid & 31;
    const int er = h ? 17 : 0;
    const int r  = h ? (r0 + 16) : (r0 - 1);
    float4 s  = make_float4(0.f,0.f,0.f,0.f);
    float4 s2 = make_float4(0.f,0.f,0.f,0.f);
    if (r >= 0 && r < H_){
      #pragma unroll
      for (int c=0;c<C_;c++){
        const float4 x = __ldg((const float4*)(img + c*HW_ + r*W_) + q);
        s.x += x.x; s.y += x.y; s.z += x.z; s.w += x.w;
        s2.x = fmaf(x.x,x.x,s2.x); s2.y = fmaf(x.y,x.y,s2.y);
        s2.z = fmaf(x.z,x.z,s2.z); s2.w = fmaf(x.w,x.w,s2.w);
      }
    }
    *((float4*)&cs [er][0] + q) = s;
    *((float4*)&cs2[er][0] + q) = s2;
  }
  __syncthreads();

  // ---- pass B: vectorized 3x3 neighborhood sums -> variance (n=72, ddof=1) ----
  #pragma unroll
  for (int it=0; it<2; it++){
    const int idx = tid + it*256;       // 0..511
    const int j   = idx >> 5;
    const int q   = idx & 31;
    const int er  = j + 1;
    const int w0  = q*4;

    float4 a1 = *((const float4*)&cs[er-1][0] + q);
    float4 a0 = *((const float4*)&cs[er  ][0] + q);
    float4 a2 = *((const float4*)&cs[er+1][0] + q);
    float4 vs;
    vs.x = a1.x+a0.x+a2.x; vs.y = a1.y+a0.y+a2.y;
    vs.z = a1.z+a0.z+a2.z; vs.w = a1.w+a0.w+a2.w;
    const float vl = (q>0)  ? cs[er-1][w0-1]+cs[er][w0-1]+cs[er+1][w0-1] : 0.f;
    const float vr = (q<31) ? cs[er-1][w0+4]+cs[er][w0+4]+cs[er+1][w0+4] : 0.f;

    float4 b1 = *((const float4*)&cs2[er-1][0] + q);
    float4 b0 = *((const float4*)&cs2[er  ][0] + q);
    float4 b2 = *((const float4*)&cs2[er+1][0] + q);
    float4 us;
    us.x = b1.x+b0.x+b2.x; us.y = b1.y+b0.y+b2.y;
    us.z = b1.z+b0.z+b2.z; us.w = b1.w+b0.w+b2.w;
    const float ul = (q>0)  ? cs2[er-1][w0-1]+cs2[er][w0-1]+cs2[er+1][w0-1] : 0.f;
    const float ur = (q<31) ? cs2[er-1][w0+4]+cs2[er][w0+4]+cs2[er+1][w0+4] : 0.f;

    const float s1_0 = vl  + vs.x + vs.y;
    const float s1_1 = vs.x + vs.y + vs.z;
    const float s1_2 = vs.y + vs.z + vs.w;
    const float s1_3 = vs.z + vs.w + vr;
    const float s2_0 = ul  + us.x + us.y;
    const float s2_1 = us.x + us.y + us.z;
    const float s2_2 = us.y + us.z + us.w;
    const float s2_3 = us.z + us.w + ur;

    motsum += (s2_0 - s1_0*s1_0*(1.0f/72.0f)) * (1.0f/71.0f);
    motsum += (s2_1 - s1_1*s1_1*(1.0f/72.0f)) * (1.0f/71.0f);
    motsum += (s2_2 - s1_2*s1_2*(1.0f/72.0f)) * (1.0f/71.0f);
    motsum += (s2_3 - s1_3*s1_3*(1.0f/72.0f)) * (1.0f/71.0f);
  }

  // ---- tail: warp reduce -> one smem fold (1 sync) ----
  #pragma unroll
  for (int c=0;c<C_;c++) chsum[c] = warpReduceSum(chsum[c]);
  #pragma unroll
  for (int c=0;c<C_;c++) chmax[c] = warpReduceMax(chmax[c]);
  difsum = warpReduceSum(difsum);
  motsum = warpReduceSum(motsum);
  if (lane == 0){
    #pragma unroll
    for (int c=0;c<C_;c++) wbuf[wrp][c]   = chsum[c];
    #pragma unroll
    for (int c=0;c<C_;c++) wbuf[wrp][8+c] = chmax[c];
    wbuf[wrp][16] = difsum;
    wbuf[wrp][17] = motsum;
  }
  __syncthreads();
  if (wrp == 0 && lane < 18){
    const int p = tb*NBAND + band;
    if (lane < 8){
      float a = 0.f;
      #pragma unroll
      for (int w=0;w<8;w++) a += wbuf[w][lane];
      g_part_chsum[p*C_+lane] = a;
    } else if (lane < 16){
      float a = -3.402823466e38f;
      #pragma unroll
      for (int w=0;w<8;w++) a = fmaxf(a, wbuf[w][lane]);
      g_part_chmax[p*C_+(lane-8)] = a;
    } else if (lane == 16){
      float a = 0.f;
      #pragma unroll
      for (int w=0;w<8;w++) a += wbuf[w][16];
      g_part_dif[p] = a;
    } else {
      float a = 0.f;
      #pragma unroll
      for (int w=0;w<8;w++) a += wbuf[w][17];
      g_part_mot[p] = a;
    }
  }
}

// ---------------------------------------------------------------------------
// Phase 2: fold band partials; tiny MLP (hidden=1) -> beta; threshold.
// ---------------------------------------------------------------------------
__device__ __forceinline__ float sigmoidf_(float x){ return 1.f/(1.f+expf(-x)); }

__global__ void phase2_kernel(const float* __restrict__ att_w1,
                              const float* __restrict__ att_w2,
                              const float* __restrict__ dw,
                              const float* __restrict__ tw,
                              const float* __restrict__ mw){
  const int tb = threadIdx.x;          // 0..255
  const int t  = tb / B_;

  float mx[C_], sm_[C_];
  #pragma unroll
  for (int c=0;c<C_;c++){ mx[c] = -3.402823466e38f; sm_[c] = 0.f; }
  float difsum = 0.f, motsum = 0.f;

  #pragma unroll
  for (int band=0; band<NBAND; band++){
    const int p = tb*NBAND + band;
    #pragma unroll
    for (int c=0;c<C_;c++){
      mx[c]  = fmaxf(mx[c], g_part_chmax[p*C_+c]);
      sm_[c] += g_part_chsum[p*C_+c];
    }
    difsum += g_part_dif[p];
    motsum += g_part_mot[p];
  }

  float csum_all = 0.f;
  float av[C_];
  #pragma unroll
  for (int c=0;c<C_;c++){
    av[c] = sm_[c] * (1.0f/(float)HW_);
    csum_all += sm_[c];
  }
  float h = 0.f;
  #pragma unroll
  for (int c=0;c<C_;c++) h += mx[c]*att_w1[c];
  #pragma unroll
  for (int c=0;c<C_;c++) h += av[c]*att_w1[C_+c];
  h = fmaxf(h, 0.f);
  #pragma unroll
  for (int c=0;c<C_;c++)
    g_beta[tb*C_+c] = 0.5f + 0.45f*sigmoidf_(h*att_w2[c]);

  const float density  = csum_all * (1.0f/((float)C_*HW_));
  const float temporal = (t==0) ? 0.f : difsum * (1.0f/((float)C_*HW_));
  const float motion   = motsum * (1.0f/(float)HW_);
  const float adj = sigmoidf_(dw[0]*density + tw[0]*temporal + mw[0]*motion) * 2.0f;
  g_thr[tb] = 1.0f + adj;
}

// ---------------------------------------------------------------------------
// Fast atan: minimax deg-11 on [-1,1] + range reduction. |err| ~2e-5.
// ---------------------------------------------------------------------------
__device__ __forceinline__ float atan_fast(float x){
  const float ax  = fabsf(x);
  const bool big  = ax > 1.0f;
  const float z   = big ? __fdividef(1.0f, ax) : ax;
  const float s   = z*z;
  float p =        -0.01172120f;
  p = fmaf(p, s,    0.05265332f);
  p = fmaf(p, s,   -0.11643287f);
  p = fmaf(p, s,    0.19354346f);
  p = fmaf(p, s,   -0.33262347f);
  p = fmaf(p, s,    0.99997726f);
  float r = z * p;
  if (big) r = 1.57079632679f - r;
  return (x < 0.0f) ? -r : r;
}

// ---------------------------------------------------------------------------
// Phase 3: fused depthwise 3x3 conv + sequential LIF scan over T.
// Warp-per-row, NO shared memory, NO barriers. Lane owns 4 columns.
// Horizontal neighbors via shuffles; vertical via direct loads (L1 hit).
// Double-buffered t+1 prefetch; v-state in registers across t.
// ---------------------------------------------------------------------------
__global__ void __launch_bounds__(256) phase3_kernel(const float* __restrict__ ev,
                                                     const float* __restrict__ conv_w,
                                                     float* __restrict__ out){
  const int tid  = threadIdx.x;
  const int lane = tid & 31;
  const int wrp  = tid >> 5;                 // 0..7
  const int r    = blockIdx.x*8 + wrp;       // row 0..127
  const int c    = blockIdx.y;               // 0..7
  const int b    = blockIdx.z;               // 0..15
  const int w0   = lane*4;

  float wk[9];
  #pragma unroll
  for (int i=0;i<9;i++) wk[i] = __ldg(conv_w + c*9 + i);

  const bool hasUp = (r > 0);
  const bool hasDn = (r < H_-1);
  const size_t rowOff = (size_t)r*W_ + w0;

  float4 v = make_float4(0.f,0.f,0.f,0.f);
  const float4 Z = make_float4(0.f,0.f,0.f,0.f);

  float4 A, Bv, Cv;      // rows r-1, r, r+1 at time t
  {
    const float* img = ev + ((size_t)b*C_ + c)*HW_;       // t = 0
    A  = hasUp ? __ldg((const float4*)(img + rowOff - W_)) : Z;
    Bv =         __ldg((const float4*)(img + rowOff));
    Cv = hasDn ? __ldg((const float4*)(img + rowOff + W_)) : Z;
  }

  for (int t=0; t<T_; t++){
    // prefetch t+1 (overlaps with compute)
    float4 An=Z, Bn=Z, Cn=Z;
    if (t+1 < T_){
      const float* img = ev + ((size_t)((t+1)*B_+b)*C_ + c)*HW_;
      if (hasUp) An = __ldg((const float4*)(img + rowOff - W_));
      Bn = __ldg((const float4*)(img + rowOff));
      if (hasDn) Cn = __ldg((const float4*)(img + rowOff + W_));
    }

    // horizontal halo via shuffles (lane 0 left = 0, lane 31 right = 0)
    float lA = __shfl_up_sync(0xffffffffu, A.w, 1);  if (lane==0)  lA = 0.f;
    float lB = __shfl_up_sync(0xffffffffu, Bv.w, 1); if (lane==0)  lB = 0.f;
    float lC = __shfl_up_sync(0xffffffffu, Cv.w, 1); if (lane==0)  lC = 0.f;
    float rA = __shfl_down_sync(0xffffffffu, A.x, 1);  if (lane==31) rA = 0.f;
    float rB = __shfl_down_sync(0xffffffffu, Bv.x, 1); if (lane==31) rB = 0.f;
    float rC = __shfl_down_sync(0xffffffffu, Cv.x, 1); if (lane==31) rC = 0.f;

    const float beta = g_beta[(t*B_+b)*C_+c];
    const float omb  = 1.f - beta;
    const float thr  = g_thr[t*B_+b];

    // 9-point conv for the 4 pixels
    float wi0 = lA*wk[0]  + A.x*wk[1]  + A.y*wk[2]
              + lB*wk[3]  + Bv.x*wk[4] + Bv.y*wk[5]
              + lC*wk[6]  + Cv.x*wk[7] + Cv.y*wk[8];
    float wi1 = A.x*wk[0] + A.y*wk[1]  + A.z*wk[2]
              + Bv.x*wk[3]+ Bv.y*wk[4] + Bv.z*wk[5]
              + Cv.x*wk[6]+ Cv.y*wk[7] + Cv.z*wk[8];
    float wi2 = A.y*wk[0] + A.z*wk[1]  + A.w*wk[2]
              + Bv.y*wk[3]+ Bv.z*wk[4] + Bv.w*wk[5]
              + Cv.y*wk[6]+ Cv.z*wk[7] + Cv.w*wk[8];
    float wi3 = A.z*wk[0] + A.w*wk[1]  + rA*wk[2]
              + Bv.z*wk[3]+ Bv.w*wk[4] + rB*wk[5]
              + Cv.z*wk[6]+ Cv.w*wk[7] + rC*wk[8];

    // LIF: charge -> atan spike -> reset; out = events * spike
    float4 o;
    {
      float vv = fmaf(beta, v.x, omb*wi0);
      const float sp = atan_fast(2.f*(vv - thr))*0.5f + 0.5f;
      v.x = (1.f - sp)*vv;  o.x = Bv.x * sp;
    }
    {
      float vv = fmaf(beta, v.y, omb*wi1);
      const float sp = atan_fast(2.f*(vv - thr))*0.5f + 0.5f;
      v.y = (1.f - sp)*vv;  o.y = Bv.y * sp;
    }
    {
      float vv = fmaf(beta, v.z, omb*wi2);
      const float sp = atan_fast(2.f*(vv - thr))*0.5f + 0.5f;
      v.z = (1.f - sp)*vv;  o.z = Bv.z * sp;
    }
    {
      float vv = fmaf(beta, v.w, omb*wi3);
      const float sp = atan_fast(2.f*(vv - thr))*0.5f + 0.5f;
      v.w = (1.f - sp)*vv;  o.w = Bv.w * sp;
    }
    *((float4*)(out + ((size_t)(t*B_+b)*C_ + c)*HW_ + rowOff)) = o;

    A = An; Bv = Bn; Cv = Cn;
  }
}

// ---------------------------------------------------------------------------
extern "C" void kernel_launch(void* const* d_in, const int* in_sizes, int n_in,
                              void* d_out, int out_size){
  const float* ev     = (const float*)d_in[0];
  const float* conv_w = (const float*)d_in[1];
  const float* att_w1 = (const float*)d_in[2];
  const float* att_w2 = (const float*)d_in[3];
  const float* dw     = (const float*)d_in[4];
  const float* tw     = (const float*)d_in[5];
  const float* mw     = (const float*)d_in[6];
  float* out = (float*)d_out;

  dim3 g1(TB_, NBAND);
  phase1_kernel<<<g1, 256>>>(ev);
  phase2_kernel<<<1, TB_>>>(att_w1, att_w2, dw, tw, mw);
  dim3 g3(H_/8, C_, B_);
  phase3_kernel<<<g3, 256>>>(ev, conv_w, out);
}